// round 8
// baseline (speedup 1.0000x reference)
#include <cuda_runtime.h>
#include <cuda_bf16.h>
#include <math.h>

#define BATCH 256
#define SEQ   512
#define INP   300
#define HID   128
#define G3    384
#define KSTEPS 19          // 19 k-steps of 16 (k padded 300 -> 304)
#define NTILES 48          // 384 / 8
#define NMT   8192         // (BATCH*SEQ)/16 m-tiles

typedef unsigned long long u64;
typedef unsigned int u32;

// ======================= globals =======================
// xg preactivations WITHOUT b_ih (gru adds it): [B, T, 3H] fp32
__device__ float g_xg[(size_t)BATCH * SEQ * G3];
// W_ih pre-packed in m16n8k16 B-fragment order:
//   [ntile][kstep][lane] -> uint4 {b0_hi, b1_hi, b0_lo, b1_lo}
__device__ uint4 g_Wfrag[NTILES * KSTEPS * 32];
// x pre-packed in m16n8k16 A-fragment order:
//   [mtile][kstep][lane] -> hi uint4 {a0,a1,a2,a3}, lo uint4
__device__ uint4 g_Afh[(size_t)NMT * KSTEPS * 32];
__device__ uint4 g_Afl[(size_t)NMT * KSTEPS * 32];

// ---- f32x2 packed FMA for gru ----
#define FMA_X2(d, a, b, c) \
    asm("fma.rn.f32x2 %0, %1, %2, %3;" : "=l"(d) : "l"(a), "l"(b), "l"(c))
__device__ __forceinline__ float2 upk(u64 v) {
    float2 r;
    asm("mov.b64 {%0,%1}, %2;" : "=f"(r.x), "=f"(r.y) : "l"(v));
    return r;
}
__device__ __forceinline__ float sigf(float x) {
    return __fdividef(1.f, 1.f + __expf(-x));
}
__device__ __forceinline__ float tanhfast(float x) {
    x = fminf(fmaxf(x, -20.f), 20.f);
    float e = __expf(2.f * x);
    return __fdividef(e - 1.f, e + 1.f);
}

// bf16 pair pack: lo half = first (lower-k) element
__device__ __forceinline__ u32 pack_bf2(float v0, float v1) {
    union { __nv_bfloat162 b; u32 u; } t;
    t.b = __halves2bfloat162(__float2bfloat16(v0), __float2bfloat16(v1));
    return t.u;
}
__device__ __forceinline__ u32 pack_bf2_lo(float v0, float v1) {
    __nv_bfloat16 h0 = __float2bfloat16(v0);
    __nv_bfloat16 h1 = __float2bfloat16(v1);
    union { __nv_bfloat162 b; u32 u; } t;
    t.b = __halves2bfloat162(__float2bfloat16(v0 - __bfloat162float(h0)),
                             __float2bfloat16(v1 - __bfloat162float(h1)));
    return t.u;
}

#define MMA_BF16(c, a0, a1, a2, a3, b0, b1)                                   \
    asm volatile("mma.sync.aligned.m16n8k16.row.col.f32.bf16.bf16.f32 "       \
                 "{%0,%1,%2,%3}, {%4,%5,%6,%7}, {%8,%9}, {%0,%1,%2,%3};"      \
                 : "+f"((c)[0]), "+f"((c)[1]), "+f"((c)[2]), "+f"((c)[3])     \
                 : "r"(a0), "r"(a1), "r"(a2), "r"(a3), "r"(b0), "r"(b1))

// ---------------------------------------------------------------------------
// Prep: W_ih [384 x 300] fp32 -> B-fragment-ordered bf16 hi/lo image.
// ---------------------------------------------------------------------------
__global__ void prep_kernel(const float* __restrict__ W) {
    int idx = blockIdx.x * blockDim.x + threadIdx.x;    // 48*19*32 = 29184
    if (idx >= NTILES * KSTEPS * 32) return;
    int nt   = idx / (KSTEPS * 32);
    int rem  = idx % (KSTEPS * 32);
    int ks   = rem >> 5;
    int lane = rem & 31;
    int n    = nt * 8 + (lane >> 2);
    int k0   = ks * 16 + 2 * (lane & 3);

    const float* wr = W + (size_t)n * INP;
    float v0 = (k0     < INP) ? wr[k0]     : 0.f;
    float v1 = (k0 + 1 < INP) ? wr[k0 + 1] : 0.f;
    float v2 = (k0 + 8 < INP) ? wr[k0 + 8] : 0.f;
    float v3 = (k0 + 9 < INP) ? wr[k0 + 9] : 0.f;

    uint4 o;
    o.x = pack_bf2(v0, v1);
    o.y = pack_bf2(v2, v3);
    o.z = pack_bf2_lo(v0, v1);
    o.w = pack_bf2_lo(v2, v3);
    g_Wfrag[idx] = o;
}

// ---------------------------------------------------------------------------
// Conv: x [131072 x 300] fp32 -> A-fragment-ordered bf16 hi/lo images.
//   a0 = rows r0 k{k0,k0+1}; a1 = r1 same; a2 = r0 k+8; a3 = r1 k+8.
// ---------------------------------------------------------------------------
__global__ void conv_kernel(const float* __restrict__ x) {
    size_t idx = (size_t)blockIdx.x * blockDim.x + threadIdx.x;  // NMT*19*32
    if (idx >= (size_t)NMT * KSTEPS * 32) return;
    int mt   = (int)(idx / (KSTEPS * 32));
    int rem  = (int)(idx % (KSTEPS * 32));
    int ks   = rem >> 5;
    int lane = rem & 31;
    int r0   = mt * 16 + (lane >> 2);
    int r1   = r0 + 8;
    int k0   = ks * 16 + 2 * (lane & 3);       // max 294; k0,k0+1 always valid

    const float* x0 = x + (size_t)r0 * INP;
    const float* x1 = x + (size_t)r1 * INP;
    float2 p0 = *(const float2*)(x0 + k0);
    float2 p1 = *(const float2*)(x1 + k0);
    float2 q0 = make_float2(0.f, 0.f);
    float2 q1 = make_float2(0.f, 0.f);
    if (k0 + 9 < INP) {
        q0 = *(const float2*)(x0 + k0 + 8);
        q1 = *(const float2*)(x1 + k0 + 8);
    } else {
        if (k0 + 8 < INP) { q0.x = x0[k0 + 8]; q1.x = x1[k0 + 8]; }
    }

    uint4 H, L;
    H.x = pack_bf2(p0.x, p0.y);  L.x = pack_bf2_lo(p0.x, p0.y);
    H.y = pack_bf2(p1.x, p1.y);  L.y = pack_bf2_lo(p1.x, p1.y);
    H.z = pack_bf2(q0.x, q0.y);  L.z = pack_bf2_lo(q0.x, q0.y);
    H.w = pack_bf2(q1.x, q1.y);  L.w = pack_bf2_lo(q1.x, q1.y);
    g_Afh[idx] = H;
    g_Afl[idx] = L;
}

// ---------------------------------------------------------------------------
// Proj: xg = x @ W^T via mma.sync bf16x3, pure fragment loads (no pack).
//   grid 1024 x 256 thr; warp owns one m-tile; N in 4 chunks of 12 n-tiles.
// ---------------------------------------------------------------------------
__global__ __launch_bounds__(256, 2) void proj_mma_kernel() {
    const int tid   = threadIdx.x;
    const int wid   = tid >> 5;
    const int lane  = tid & 31;
    const int gid   = lane >> 2;
    const int tig   = lane & 3;
    const int mtile = blockIdx.x * 8 + wid;

    const uint4* Ah = g_Afh + ((size_t)mtile * KSTEPS) * 32 + lane;
    const uint4* Al = g_Afl + ((size_t)mtile * KSTEPS) * 32 + lane;
    const int r0 = mtile * 16 + gid;
    const int r1 = r0 + 8;

    for (int nc = 0; nc < 4; nc++) {
        float C[12][4];
        #pragma unroll
        for (int i = 0; i < 12; i++)
            #pragma unroll
            for (int j = 0; j < 4; j++) C[i][j] = 0.f;

        for (int ks = 0; ks < KSTEPS; ks++) {
            uint4 FH = Ah[(size_t)ks * 32];
            uint4 FL = Al[(size_t)ks * 32];
            const uint4* bp = g_Wfrag + ((size_t)(nc * 12) * KSTEPS + ks) * 32 + lane;
            #pragma unroll
            for (int ntl = 0; ntl < 12; ntl++) {
                uint4 B = bp[(size_t)ntl * KSTEPS * 32];
                MMA_BF16(C[ntl], FH.x, FH.y, FH.z, FH.w, B.x, B.y);  // hi*hi
                MMA_BF16(C[ntl], FH.x, FH.y, FH.z, FH.w, B.z, B.w);  // hi*lo
                MMA_BF16(C[ntl], FL.x, FL.y, FL.z, FL.w, B.x, B.y);  // lo*hi
            }
        }
        #pragma unroll
        for (int ntl = 0; ntl < 12; ntl++) {
            const int n0 = (nc * 12 + ntl) * 8 + 2 * tig;
            *(float2*)(g_xg + (size_t)r0 * G3 + n0) = make_float2(C[ntl][0], C[ntl][1]);
            *(float2*)(g_xg + (size_t)r1 * G3 + n0) = make_float2(C[ntl][2], C[ntl][3]);
        }
    }
}

// ---------------------------------------------------------------------------
// GRU recurrence, batch-pipelined. 2 batch rows/CTA, grid=128 (one wave).
//   Phase A: dot(batch0) || gates(batch1, step t-1)  [warps 8-11]
//   Phase B: dot(batch1) || gates(batch0, step t)    [warps 0-3]
//   Gate work + xg prefetch hidden under the FMA-saturated dot phases.
// ---------------------------------------------------------------------------
__global__ __launch_bounds__(384) void gru_kernel(const float* __restrict__ W_hh,
                                                  const float* __restrict__ b_ih,
                                                  const float* __restrict__ b_hh,
                                                  const float* __restrict__ W_out,
                                                  const float* __restrict__ b_out,
                                                  float* __restrict__ out) {
    __shared__ __align__(16) float h0s[HID];
    __shared__ __align__(16) float h1s[HID];
    __shared__ float hg0s[G3], hg1s[G3];
    __shared__ float lg[4];

    const int g  = threadIdx.x;
    const int b0 = blockIdx.x * 2;

    u64 wp[HID / 2];
    {
        const ulonglong2* wr = (const ulonglong2*)(W_hh + g * HID);
        #pragma unroll
        for (int q = 0; q < HID / 4; q++) {
            ulonglong2 t = wr[q];
            wp[2 * q]     = t.x;
            wp[2 * q + 1] = t.y;
        }
    }
    const float bh = b_hh[g];

    if (g < HID) { h0s[g] = 0.f; h1s[g] = 0.f; }
    __syncthreads();

    const bool isA = (g < 128);             // gates for batch0 (phase B)
    const bool isB = (g >= 256);            // gates for batch1 (phase A, lagged)
    const int  j   = isB ? (g - 256) : (g & 127);
    const float* xqA = g_xg + (size_t)b0 * SEQ * G3 + j;          // batch0
    const float* xqB = g_xg + (size_t)(b0 + 1) * SEQ * G3 + j;    // batch1
    float bi0 = 0.f, bi1 = 0.f, bi2 = 0.f;
    float xa0 = 0.f, xa1 = 0.f, xa2 = 0.f;   // xg0[t]   (gateA at phase B of t)
    float xb0 = 0.f, xb1 = 0.f, xb2 = 0.f;   // xg1[t-1] (gateB at phase A of t)
    if (isA || isB) {
        bi0 = b_ih[j]; bi1 = b_ih[j + 128]; bi2 = b_ih[j + 256];
    }
    if (isA) { xa0 = xqA[0]; xa1 = xqA[128]; xa2 = xqA[256]; }
    if (isB) { xb0 = xqB[0]; xb1 = xqB[128]; xb2 = xqB[256]; }

    for (int t = 0; t < SEQ; t++) {
        // ===== phase A: gates(batch1, t-1) + dot(batch0) =====
        if (isB && t > 0) {
            float r = sigf(xb0 + bi0 + hg1s[j]);
            float z = sigf(xb1 + bi1 + hg1s[j + 128]);
            float n = tanhfast(xb2 + bi2 + r * hg1s[j + 256]);
            h1s[j] = (1.f - z) * n + z * h1s[j];
            const float* p = xqB + (size_t)t * G3;   // xg1[t] for next phase A
            xb0 = p[0]; xb1 = p[128]; xb2 = p[256];
        }
        {
            u64 a0 = 0ULL, a1 = 0ULL;
            const ulonglong2* h4 = (const ulonglong2*)h0s;
            #pragma unroll
            for (int q = 0; q < HID / 4; q++) {
                ulonglong2 hv = h4[q];
                FMA_X2(a0, wp[2 * q],     hv.x, a0);
                FMA_X2(a1, wp[2 * q + 1], hv.y, a1);
            }
            float2 s0 = upk(a0), s1 = upk(a1);
            hg0s[g] = (s0.x + s0.y) + (s1.x + s1.y) + bh;
        }
        __syncthreads();

        // ===== phase B: gates(batch0, t) + dot(batch1) =====
        if (isA) {
            float r = sigf(xa0 + bi0 + hg0s[j]);
            float z = sigf(xa1 + bi1 + hg0s[j + 128]);
            float n = tanhfast(xa2 + bi2 + r * hg0s[j + 256]);
            h0s[j] = (1.f - z) * n + z * h0s[j];
            if (t + 1 < SEQ) {
                const float* p = xqA + (size_t)(t + 1) * G3;
                xa0 = p[0]; xa1 = p[128]; xa2 = p[256];
            }
        }
        {
            u64 a0 = 0ULL, a1 = 0ULL;
            const ulonglong2* h4 = (const ulonglong2*)h1s;
            #pragma unroll
            for (int q = 0; q < HID / 4; q++) {
                ulonglong2 hv = h4[q];
                FMA_X2(a0, wp[2 * q],     hv.x, a0);
                FMA_X2(a1, wp[2 * q + 1], hv.y, a1);
            }
            float2 s0 = upk(a0), s1 = upk(a1);
            hg1s[g] = (s0.x + s0.y) + (s1.x + s1.y) + bh;
        }
        __syncthreads();
    }

    // ===== drain: gates(batch1, SEQ-1) =====
    if (isB) {
        float r = sigf(xb0 + bi0 + hg1s[j]);
        float z = sigf(xb1 + bi1 + hg1s[j + 128]);
        float n = tanhfast(xb2 + bi2 + r * hg1s[j + 256]);
        h1s[j] = (1.f - z) * n + z * h1s[j];
    }
    __syncthreads();

    // ---- fused classifier: relu -> linear(2) -> log_softmax, both batches ----
    if (g < 4) {
        const int cls = g & 1;
        const float* hS = (g >> 1) ? h1s : h0s;
        const float* wo = W_out + cls * HID;
        float s = 0.f;
        #pragma unroll
        for (int k = 0; k < HID; k++) s = fmaf(wo[k], fmaxf(hS[k], 0.f), s);
        lg[g] = s + b_out[cls];
    }
    __syncthreads();
    if (g < 2) {
        float l0 = lg[2 * g], l1 = lg[2 * g + 1];
        float mx = fmaxf(l0, l1);
        float lse = mx + logf(expf(l0 - mx) + expf(l1 - mx));
        out[(b0 + g) * 2 + 0] = l0 - lse;
        out[(b0 + g) * 2 + 1] = l1 - lse;
    }
}

// ---------------------------------------------------------------------------
extern "C" void kernel_launch(void* const* d_in, const int* in_sizes, int n_in,
                              void* d_out, int out_size) {
    const float* x     = (const float*)d_in[0];
    const float* W_ih  = (const float*)d_in[1];
    const float* W_hh  = (const float*)d_in[2];
    const float* b_ih  = (const float*)d_in[3];
    const float* b_hh  = (const float*)d_in[4];
    const float* W_out = (const float*)d_in[5];
    const float* b_out = (const float*)d_in[6];
    float* out = (float*)d_out;

    prep_kernel<<<(NTILES * KSTEPS * 32 + 255) / 256, 256>>>(W_ih);
    conv_kernel<<<(int)(((size_t)NMT * KSTEPS * 32 + 255) / 256), 256>>>(x);
    proj_mma_kernel<<<(BATCH * SEQ) / 128, 256>>>();
    gru_kernel<<<BATCH / 2, 384>>>(W_hh, b_ih, b_hh, W_out, b_out, out);
}

// round 9
// speedup vs baseline: 1.1098x; 1.1098x over previous
#include <cuda_runtime.h>
#include <cuda_bf16.h>
#include <math.h>

#define BATCH 256
#define SEQ   512
#define INP   300
#define HID   128
#define G3    384
#define KSTEPS 19          // 19 k-steps of 16 (k padded 300 -> 304)
#define NTILES 48          // 384 / 8
#define NMT   8192         // (BATCH*SEQ)/16 m-tiles

typedef unsigned long long u64;
typedef unsigned int u32;

// ======================= globals =======================
// xg preactivations WITHOUT b_ih (gru adds it): [B, T, 3H] fp32
__device__ float g_xg[(size_t)BATCH * SEQ * G3];
// W_ih pre-packed in m16n8k16 B-fragment order:
//   [ntile][kstep][lane] -> uint4 {b0_hi, b1_hi, b0_lo, b1_lo}
__device__ uint4 g_Wfrag[NTILES * KSTEPS * 32];
// x pre-packed in m16n8k16 A-fragment order:
//   [mtile][kstep][lane] -> hi uint4 {a0,a1,a2,a3}, lo uint4
__device__ uint4 g_Afh[(size_t)NMT * KSTEPS * 32];
__device__ uint4 g_Afl[(size_t)NMT * KSTEPS * 32];

// ---- f32x2 packed FMA for gru ----
#define FMA_X2(d, a, b, c) \
    asm("fma.rn.f32x2 %0, %1, %2, %3;" : "=l"(d) : "l"(a), "l"(b), "l"(c))
__device__ __forceinline__ float2 upk(u64 v) {
    float2 r;
    asm("mov.b64 {%0,%1}, %2;" : "=f"(r.x), "=f"(r.y) : "l"(v));
    return r;
}
__device__ __forceinline__ float sigf(float x) {
    return __fdividef(1.f, 1.f + __expf(-x));
}
__device__ __forceinline__ float tanhfast(float x) {
    x = fminf(fmaxf(x, -20.f), 20.f);
    float e = __expf(2.f * x);
    return __fdividef(e - 1.f, e + 1.f);
}

// bf16 pair pack: lo half = first (lower-k) element
__device__ __forceinline__ u32 pack_bf2(float v0, float v1) {
    union { __nv_bfloat162 b; u32 u; } t;
    t.b = __halves2bfloat162(__float2bfloat16(v0), __float2bfloat16(v1));
    return t.u;
}
__device__ __forceinline__ u32 pack_bf2_lo(float v0, float v1) {
    __nv_bfloat16 h0 = __float2bfloat16(v0);
    __nv_bfloat16 h1 = __float2bfloat16(v1);
    union { __nv_bfloat162 b; u32 u; } t;
    t.b = __halves2bfloat162(__float2bfloat16(v0 - __bfloat162float(h0)),
                             __float2bfloat16(v1 - __bfloat162float(h1)));
    return t.u;
}

#define MMA_BF16(c, a0, a1, a2, a3, b0, b1)                                   \
    asm volatile("mma.sync.aligned.m16n8k16.row.col.f32.bf16.bf16.f32 "       \
                 "{%0,%1,%2,%3}, {%4,%5,%6,%7}, {%8,%9}, {%0,%1,%2,%3};"      \
                 : "+f"((c)[0]), "+f"((c)[1]), "+f"((c)[2]), "+f"((c)[3])     \
                 : "r"(a0), "r"(a1), "r"(a2), "r"(a3), "r"(b0), "r"(b1))

// ---------------------------------------------------------------------------
// Prep: W_ih [384 x 300] fp32 -> B-fragment-ordered bf16 hi/lo image.
// ---------------------------------------------------------------------------
__global__ void prep_kernel(const float* __restrict__ W) {
    int idx = blockIdx.x * blockDim.x + threadIdx.x;    // 48*19*32 = 29184
    if (idx >= NTILES * KSTEPS * 32) return;
    int nt   = idx / (KSTEPS * 32);
    int rem  = idx % (KSTEPS * 32);
    int ks   = rem >> 5;
    int lane = rem & 31;
    int n    = nt * 8 + (lane >> 2);
    int k0   = ks * 16 + 2 * (lane & 3);

    const float* wr = W + (size_t)n * INP;
    float v0 = (k0     < INP) ? wr[k0]     : 0.f;
    float v1 = (k0 + 1 < INP) ? wr[k0 + 1] : 0.f;
    float v2 = (k0 + 8 < INP) ? wr[k0 + 8] : 0.f;
    float v3 = (k0 + 9 < INP) ? wr[k0 + 9] : 0.f;

    uint4 o;
    o.x = pack_bf2(v0, v1);
    o.y = pack_bf2(v2, v3);
    o.z = pack_bf2_lo(v0, v1);
    o.w = pack_bf2_lo(v2, v3);
    g_Wfrag[idx] = o;
}

// ---------------------------------------------------------------------------
// Conv: x [131072 x 300] fp32 -> A-fragment-ordered bf16 hi/lo images.
// ---------------------------------------------------------------------------
__global__ void conv_kernel(const float* __restrict__ x) {
    size_t idx = (size_t)blockIdx.x * blockDim.x + threadIdx.x;  // NMT*19*32
    if (idx >= (size_t)NMT * KSTEPS * 32) return;
    int mt   = (int)(idx / (KSTEPS * 32));
    int rem  = (int)(idx % (KSTEPS * 32));
    int ks   = rem >> 5;
    int lane = rem & 31;
    int r0   = mt * 16 + (lane >> 2);
    int r1   = r0 + 8;
    int k0   = ks * 16 + 2 * (lane & 3);       // max 294; k0,k0+1 always valid

    const float* x0 = x + (size_t)r0 * INP;
    const float* x1 = x + (size_t)r1 * INP;
    float2 p0 = *(const float2*)(x0 + k0);
    float2 p1 = *(const float2*)(x1 + k0);
    float2 q0 = make_float2(0.f, 0.f);
    float2 q1 = make_float2(0.f, 0.f);
    if (k0 + 9 < INP) {
        q0 = *(const float2*)(x0 + k0 + 8);
        q1 = *(const float2*)(x1 + k0 + 8);
    } else {
        if (k0 + 8 < INP) { q0.x = x0[k0 + 8]; q1.x = x1[k0 + 8]; }
    }

    uint4 H, L;
    H.x = pack_bf2(p0.x, p0.y);  L.x = pack_bf2_lo(p0.x, p0.y);
    H.y = pack_bf2(p1.x, p1.y);  L.y = pack_bf2_lo(p1.x, p1.y);
    H.z = pack_bf2(q0.x, q0.y);  L.z = pack_bf2_lo(q0.x, q0.y);
    H.w = pack_bf2(q1.x, q1.y);  L.w = pack_bf2_lo(q1.x, q1.y);
    g_Afh[idx] = H;
    g_Afl[idx] = L;
}

// ---------------------------------------------------------------------------
// Proj: xg = x @ W^T via mma.sync bf16x3, pure fragment loads (no pack).
// ---------------------------------------------------------------------------
__global__ __launch_bounds__(256, 2) void proj_mma_kernel() {
    const int tid   = threadIdx.x;
    const int wid   = tid >> 5;
    const int lane  = tid & 31;
    const int gid   = lane >> 2;
    const int tig   = lane & 3;
    const int mtile = blockIdx.x * 8 + wid;

    const uint4* Ah = g_Afh + ((size_t)mtile * KSTEPS) * 32 + lane;
    const uint4* Al = g_Afl + ((size_t)mtile * KSTEPS) * 32 + lane;
    const int r0 = mtile * 16 + gid;
    const int r1 = r0 + 8;

    for (int nc = 0; nc < 4; nc++) {
        float C[12][4];
        #pragma unroll
        for (int i = 0; i < 12; i++)
            #pragma unroll
            for (int j = 0; j < 4; j++) C[i][j] = 0.f;

        for (int ks = 0; ks < KSTEPS; ks++) {
            uint4 FH = Ah[(size_t)ks * 32];
            uint4 FL = Al[(size_t)ks * 32];
            const uint4* bp = g_Wfrag + ((size_t)(nc * 12) * KSTEPS + ks) * 32 + lane;
            #pragma unroll
            for (int ntl = 0; ntl < 12; ntl++) {
                uint4 B = bp[(size_t)ntl * KSTEPS * 32];
                MMA_BF16(C[ntl], FH.x, FH.y, FH.z, FH.w, B.x, B.y);  // hi*hi
                MMA_BF16(C[ntl], FH.x, FH.y, FH.z, FH.w, B.z, B.w);  // hi*lo
                MMA_BF16(C[ntl], FL.x, FL.y, FL.z, FL.w, B.x, B.y);  // lo*hi
            }
        }
        #pragma unroll
        for (int ntl = 0; ntl < 12; ntl++) {
            const int n0 = (nc * 12 + ntl) * 8 + 2 * tig;
            *(float2*)(g_xg + (size_t)r0 * G3 + n0) = make_float2(C[ntl][0], C[ntl][1]);
            *(float2*)(g_xg + (size_t)r1 * G3 + n0) = make_float2(C[ntl][2], C[ntl][3]);
        }
    }
}

// ---------------------------------------------------------------------------
// GRU recurrence (R7/R5 structure — the measured-539us local optimum).
// 2 batch rows/CTA, grid=128 (one wave); W_hh row in 64 f32x2 regs; FFMA2
// dots for both batches between one barrier pair; MUFU gates; b_ih in regs;
// xg prefetched from global one step ahead.
// ---------------------------------------------------------------------------
__global__ __launch_bounds__(384) void gru_kernel(const float* __restrict__ W_hh,
                                                  const float* __restrict__ b_ih,
                                                  const float* __restrict__ b_hh,
                                                  const float* __restrict__ W_out,
                                                  const float* __restrict__ b_out,
                                                  float* __restrict__ out) {
    __shared__ __align__(16) float h0s[HID];
    __shared__ __align__(16) float h1s[HID];
    __shared__ float hg0s[G3], hg1s[G3];
    __shared__ float lg[4];

    const int g  = threadIdx.x;
    const int b0 = blockIdx.x * 2;

    u64 wp[HID / 2];
    {
        const ulonglong2* wr = (const ulonglong2*)(W_hh + g * HID);
        #pragma unroll
        for (int q = 0; q < HID / 4; q++) {
            ulonglong2 t = wr[q];
            wp[2 * q]     = t.x;
            wp[2 * q + 1] = t.y;
        }
    }
    const float bh = b_hh[g];

    if (g < HID) { h0s[g] = 0.f; h1s[g] = 0.f; }
    __syncthreads();

    const int j = g & (HID - 1);
    const float* xq = g_xg + (size_t)(b0 + (g >> 7)) * SEQ * G3 + j;
    float x0 = 0.f, x1 = 0.f, x2 = 0.f, bi0 = 0.f, bi1 = 0.f, bi2 = 0.f;
    if (g < 256) {
        bi0 = b_ih[j]; bi1 = b_ih[j + HID]; bi2 = b_ih[j + 2 * HID];
        x0 = xq[0]; x1 = xq[HID]; x2 = xq[2 * HID];
    }

    for (int t = 0; t < SEQ; t++) {
        float nx0 = 0.f, nx1 = 0.f, nx2 = 0.f;
        if (g < 256 && t + 1 < SEQ) {
            const float* p = xq + (size_t)(t + 1) * G3;
            nx0 = p[0]; nx1 = p[HID]; nx2 = p[2 * HID];
        }

        u64 a0 = 0ULL, a1 = 0ULL, c0 = 0ULL, c1 = 0ULL;
        const ulonglong2* h04 = (const ulonglong2*)h0s;
        const ulonglong2* h14 = (const ulonglong2*)h1s;
        #pragma unroll
        for (int q = 0; q < HID / 4; q++) {
            ulonglong2 hv0 = h04[q];
            ulonglong2 hv1 = h14[q];
            FMA_X2(a0, wp[2 * q],     hv0.x, a0);
            FMA_X2(a1, wp[2 * q + 1], hv0.y, a1);
            FMA_X2(c0, wp[2 * q],     hv1.x, c0);
            FMA_X2(c1, wp[2 * q + 1], hv1.y, c1);
        }
        {
            float2 s0 = upk(a0), s1 = upk(a1);
            hg0s[g] = (s0.x + s0.y) + (s1.x + s1.y) + bh;
            float2 s2 = upk(c0), s3 = upk(c1);
            hg1s[g] = (s2.x + s2.y) + (s3.x + s3.y) + bh;
        }
        __syncthreads();

        if (g < 256) {
            float*       hS  = (g < HID) ? h0s  : h1s;
            const float* hgS = (g < HID) ? hg0s : hg1s;
            float r  = sigf(x0 + bi0 + hgS[j]);
            float z  = sigf(x1 + bi1 + hgS[j + HID]);
            float n  = tanhfast(x2 + bi2 + r * hgS[j + 2 * HID]);
            hS[j] = (1.f - z) * n + z * hS[j];
        }
        __syncthreads();

        x0 = nx0; x1 = nx1; x2 = nx2;
    }

    if (g < 4) {
        const int cls = g & 1;
        const float* hS = (g >> 1) ? h1s : h0s;
        const float* wo = W_out + cls * HID;
        float s = 0.f;
        #pragma unroll
        for (int k = 0; k < HID; k++) s = fmaf(wo[k], fmaxf(hS[k], 0.f), s);
        lg[g] = s + b_out[cls];
    }
    __syncthreads();
    if (g < 2) {
        float l0 = lg[2 * g], l1 = lg[2 * g + 1];
        float mx = fmaxf(l0, l1);
        float lse = mx + logf(expf(l0 - mx) + expf(l1 - mx));
        out[(b0 + g) * 2 + 0] = l0 - lse;
        out[(b0 + g) * 2 + 1] = l1 - lse;
    }
}

// ---------------------------------------------------------------------------
extern "C" void kernel_launch(void* const* d_in, const int* in_sizes, int n_in,
                              void* d_out, int out_size) {
    const float* x     = (const float*)d_in[0];
    const float* W_ih  = (const float*)d_in[1];
    const float* W_hh  = (const float*)d_in[2];
    const float* b_ih  = (const float*)d_in[3];
    const float* b_hh  = (const float*)d_in[4];
    const float* W_out = (const float*)d_in[5];
    const float* b_out = (const float*)d_in[6];
    float* out = (float*)d_out;

    prep_kernel<<<(NTILES * KSTEPS * 32 + 255) / 256, 256>>>(W_ih);
    conv_kernel<<<(int)(((size_t)NMT * KSTEPS * 32 + 255) / 256), 256>>>(x);
    proj_mma_kernel<<<(BATCH * SEQ) / 128, 256>>>();
    gru_kernel<<<BATCH / 2, 384>>>(W_hh, b_ih, b_hh, W_out, b_out, out);
}